// round 7
// baseline (speedup 1.0000x reference)
#include <cuda_runtime.h>

#define LATENT  10
#define MAXLEN  80
#define BATCH   512
#define NSTEPS  100
#define HID     64
#define DTC     0.01f

typedef unsigned long long u64;
typedef unsigned int u32;

// ---------------- packed f32x2 helpers (sm_100+) ----------------
__device__ __forceinline__ u64 pk(float x, float y) {
    u64 r; asm("mov.b64 %0, {%1, %2};" : "=l"(r) : "f"(x), "f"(y)); return r;
}
__device__ __forceinline__ void upk(u64 a, float& x, float& y) {
    asm("mov.b64 {%0, %1}, %2;" : "=f"(x), "=f"(y) : "l"(a));
}
__device__ __forceinline__ u64 fma2_(u64 a, u64 b, u64 c) {
    u64 d; asm("fma.rn.f32x2 %0, %1, %2, %3;" : "=l"(d) : "l"(a), "l"(b), "l"(c)); return d;
}
__device__ __forceinline__ u64 mul2_(u64 a, u64 b) {
    u64 d; asm("mul.rn.f32x2 %0, %1, %2;" : "=l"(d) : "l"(a), "l"(b)); return d;
}
__device__ __forceinline__ u64 sub2_(u64 a, u64 b) {
    u64 d; asm("sub.rn.f32x2 %0, %1, %2;" : "=l"(d) : "l"(a), "l"(b)); return d;
}

// ---------------- tf32 helpers ----------------
__device__ __forceinline__ u32 cvt_tf32(float x) {
    u32 r; asm("cvt.rna.tf32.f32 %0, %1;" : "=r"(r) : "f"(x)); return r;
}
__device__ __forceinline__ void split_tf32(float x, u32& hi, u32& lo) {
    hi = cvt_tf32(x);
    lo = cvt_tf32(x - __uint_as_float(hi));
}

__device__ __forceinline__ void mma8(float* c, u32 a0, u32 a1, u32 a2, u32 a3,
                                     u32 b0, u32 b1) {
    asm("mma.sync.aligned.m16n8k8.row.col.f32.tf32.tf32.f32 "
        "{%0,%1,%2,%3}, {%4,%5,%6,%7}, {%8,%9}, {%0,%1,%2,%3};"
        : "+f"(c[0]), "+f"(c[1]), "+f"(c[2]), "+f"(c[3])
        : "r"(a0), "r"(a1), "r"(a2), "r"(a3), "r"(b0), "r"(b1));
}

// per-(chain, d) SDE constants
__device__ __forceinline__ void prep_cd(const float* __restrict__ zm,
                                        const float* __restrict__ zlv,
                                        int bb, int l, int d,
                                        float& mu, float& sinv, float& ssd) {
    const float* zmr = zm  + ((size_t)bb * MAXLEN + l) * LATENT;
    const float* zvr = zlv + ((size_t)bb * MAXLEN + l) * LATENT;
    float zmc = zmr[d];
    float zmp = (l > 0) ? zmr[d - LATENT] : 0.f;
    mu = zmc - zmp;
    float av = (l > 0) ? zvr[d - LATENT] : 0.f;
    float bv = zvr[d];
    float mx = fmaxf(av, bv);
    float sg = mx + log1pf(expf(-fabsf(av - bv)));   // logaddexp
    float sstd = expf(0.5f * sg);
    sinv = 1.f / sg;
    ssd  = sstd * 0.1f;                              // sigma_std * sqrt(dt)
}

// One warp = 16 chains (same l). MLP via m16n8k8 tf32 MMA, weights in
// register B-fragments (x3 precision split). SDE state lives in the MMA
// C-layout with the latent dim internally permuted so that the score
// output fragment IS the next step's A fragment (zero-cost chaining).
//   lane: r = lane>>2 (chain rows r, r+8), gc = lane&3.
//   state pair [nt][half]: nt0 -> d (gc, gc+4); nt1 -> d (8+gc valid gc<2, pad).
__global__ void __launch_bounds__(32)
vae_mma_kernel(const float* __restrict__ zm,
               const float* __restrict__ zlv,
               const float* __restrict__ W1,
               const float* __restrict__ b1,
               const float* __restrict__ W2,
               const float* __restrict__ b2,
               const float* __restrict__ noise,
               float* __restrict__ out)
{
    const int lane = threadIdx.x;
    const int r  = lane >> 2;
    const int gc = lane & 3;
    const int base = blockIdx.x * 16;
    const int l   = base >> 9;          // uniform per warp (16 | 512)
    const int bb0 = base & 511;
    const int cA  = bb0 + r;
    const int cB  = bb0 + r + 8;

    // hidden-unit permutation: B-col n (=r) -> j_local
    const int jl = (r & 1) ? (r >> 1) + 4 : (r >> 1);

    // ---- static weight fragments (x3 split) ----
    u32 B1h0[8][2], B1l0[8][2];       // layer1 kt0 (features 0-7)
    u32 B1h1[8],    B1l1[8];          // layer1 kt1 reg0 (features 8-11); reg1 = 0
    u32 B2h[8][2][2], B2l[8][2][2];   // layer2 [jt][nt][reg]

#pragma unroll
    for (int jt = 0; jt < 8; jt++) {
        int j = 8 * jt + jl;
        split_tf32(W1[gc * HID + j],       B1h0[jt][0], B1l0[jt][0]);
        split_tf32(W1[(gc + 4) * HID + j], B1h0[jt][1], B1l0[jt][1]);
        float wt = (gc == 3) ? b1[j] : W1[(8 + gc) * HID + j];
        split_tf32(wt, B1h1[jt], B1l1[jt]);
#pragma unroll
        for (int nt = 0; nt < 2; nt++) {
            int d = (nt == 0) ? jl : ((jl < 2) ? 8 + jl : -1);
            float v0 = (d >= 0) ? W2[(8 * jt + gc) * LATENT + d]     : 0.f;
            float v1 = (d >= 0) ? W2[(8 * jt + gc + 4) * LATENT + d] : 0.f;
            split_tf32(v0, B2h[jt][nt][0], B2l[jt][nt][0]);
            split_tf32(v1, B2h[jt][nt][1], B2l[jt][nt][1]);
        }
    }

    // ---- SDE state in fragment layout ----
    u64 xt[2][2], mu2[2][2], sinv2[2][2], ssd2[2][2], hv2[2][2], err2[2][2];
#pragma unroll
    for (int h = 0; h < 2; h++) {
        int bb = (h == 0) ? cA : cB;
        float m0, s0, w0, m1, s1, w1;
        prep_cd(zm, zlv, bb, l, gc,     m0, s0, w0);
        prep_cd(zm, zlv, bb, l, gc + 4, m1, s1, w1);
        mu2[0][h]   = pk(m0, m1);
        sinv2[0][h] = pk(s0, s1);
        ssd2[0][h]  = pk(w0, w1);
        xt[0][h]    = mu2[0][h];
        err2[0][h]  = 0ULL;
        if (gc < 2) {
            prep_cd(zm, zlv, bb, l, 8 + gc, m0, s0, w0);
        } else { m0 = 0.f; s0 = 0.f; w0 = 0.f; }
        mu2[1][h]   = pk(m0, 0.f);
        sinv2[1][h] = pk(s0, 0.f);
        ssd2[1][h]  = pk(w0, 0.f);
        xt[1][h]    = mu2[1][h];
        err2[1][h]  = 0ULL;
    }
    const u64 dt2 = pk(DTC, DTC);
    const u64 h05 = pk(0.5f, 0.5f);
#pragma unroll
    for (int nt = 0; nt < 2; nt++)
#pragma unroll
        for (int h = 0; h < 2; h++)
            hv2[nt][h] = mul2_(mul2_(ssd2[nt][h], ssd2[nt][h]), h05);  // 0.5*var*dt

    // bias values in S C-layout
    const float bs0 = b2[gc];
    const float bs1 = b2[gc + 4];
    const float bs2 = (gc < 2) ? b2[8 + gc] : 0.f;

    const float* nzbase = noise + (size_t)l * NSTEPS * BATCH * LATENT;

#pragma unroll 1
    for (int s = 0; s < NSTEPS; s++) {
        // noise for this step (fragment layout, scalar gathers)
        const float* nA = nzbase + (size_t)s * BATCH * LATENT + cA * LATENT;
        const float* nB = nA + 8 * LATENT;
        u64 nz00 = pk(nA[gc], nA[gc + 4]);
        u64 nz01 = pk(nB[gc], nB[gc + 4]);
        u64 nz10 = (gc < 2) ? pk(nA[8 + gc], 0.f) : 0ULL;
        u64 nz11 = (gc < 2) ? pk(nB[8 + gc], 0.f) : 0ULL;

        const float tt = (float)(l + s) * DTC;

        // A1 kt0 = xt state (C-layout == A-layout by construction)
        float xA0, xA1, xB0, xB1;
        upk(xt[0][0], xA0, xA1);
        upk(xt[0][1], xB0, xB1);
        u32 a0h, a0l, a1h, a1l, a2h, a2l, a3h, a3l;
        split_tf32(xA0, a0h, a0l);
        split_tf32(xB0, a1h, a1l);
        split_tf32(xA1, a2h, a2l);
        split_tf32(xB1, a3h, a3l);

        // A1 kt1: cols 8+gc = (xt8, xt9, t, 1); cols 12+gc = 0
        float xA8, xB8, dmy;
        upk(xt[1][0], xA8, dmy);
        upk(xt[1][1], xB8, dmy);
        float sA0 = __shfl_sync(0xffffffffu, xA8, lane & ~3);
        float sA1 = __shfl_sync(0xffffffffu, xA8, (lane & ~3) | 1);
        float sB0 = __shfl_sync(0xffffffffu, xB8, lane & ~3);
        float sB1 = __shfl_sync(0xffffffffu, xB8, (lane & ~3) | 1);
        float f0 = (gc == 0) ? sA0 : (gc == 1) ? sA1 : (gc == 2) ? tt : 1.0f;
        float f1 = (gc == 0) ? sB0 : (gc == 1) ? sB1 : (gc == 2) ? tt : 1.0f;
        u32 e0h, e0l, e1h, e1l;
        split_tf32(f0, e0h, e0l);
        split_tf32(f1, e1h, e1l);

        // layer-2 accumulators (separate to shorten mma chains)
        float Sa[2][4] = {{bs0, bs1, bs0, bs1}, {bs2, 0.f, bs2, 0.f}};
        float Sb[2][4] = {{0.f,0.f,0.f,0.f},{0.f,0.f,0.f,0.f}};
        float Sc[2][4] = {{0.f,0.f,0.f,0.f},{0.f,0.f,0.f,0.f}};

#pragma unroll
        for (int jt = 0; jt < 8; jt++) {
            float C[4]  = {0.f, 0.f, 0.f, 0.f};
            float Ce[4] = {0.f, 0.f, 0.f, 0.f};
            mma8(C,  a0h, a1h, a2h, a3h, B1h0[jt][0], B1h0[jt][1]);   // hi*hi kt0
            mma8(C,  e0h, e1h, 0u,  0u,  B1h1[jt],    0u);            // hi*hi kt1
            mma8(Ce, a0h, a1h, a2h, a3h, B1l0[jt][0], B1l0[jt][1]);   // hi*lo kt0
            mma8(Ce, a0l, a1l, a2l, a3l, B1h0[jt][0], B1h0[jt][1]);   // lo*hi kt0
            mma8(Ce, e0h, e1h, 0u,  0u,  B1l1[jt],    0u);            // hi*lo kt1
            mma8(Ce, e0l, e1l, 0u,  0u,  B1h1[jt],    0u);            // lo*hi kt1

            float h0 = fmaxf(C[0] + Ce[0], 0.f);
            float h1 = fmaxf(C[1] + Ce[1], 0.f);
            float h2 = fmaxf(C[2] + Ce[2], 0.f);
            float h3 = fmaxf(C[3] + Ce[3], 0.f);

            // H C-fragment -> A2 fragment: (a0,a1,a2,a3) = (c0,c2,c1,c3)
            u32 H0h, H0l, H1h, H1l, H2h, H2l, H3h, H3l;
            split_tf32(h0, H0h, H0l);
            split_tf32(h2, H1h, H1l);
            split_tf32(h1, H2h, H2l);
            split_tf32(h3, H3h, H3l);

#pragma unroll
            for (int nt = 0; nt < 2; nt++) {
                mma8(Sa[nt], H0h, H1h, H2h, H3h, B2h[jt][nt][0], B2h[jt][nt][1]);
                mma8(Sb[nt], H0h, H1h, H2h, H3h, B2l[jt][nt][0], B2l[jt][nt][1]);
                mma8(Sc[nt], H0l, H1l, H2l, H3l, B2h[jt][nt][0], B2h[jt][nt][1]);
            }
        }

        // combine x3 partial scores -> packed (d0,d1) pairs
        u64 sc[2][2];
#pragma unroll
        for (int nt = 0; nt < 2; nt++) {
            sc[nt][0] = pk(Sa[nt][0] + Sb[nt][0] + Sc[nt][0],
                           Sa[nt][1] + Sb[nt][1] + Sc[nt][1]);
            sc[nt][1] = pk(Sa[nt][2] + Sb[nt][2] + Sc[nt][2],
                           Sa[nt][3] + Sb[nt][3] + Sc[nt][3]);
        }

        // SDE update + score error (packed)
        u64 nz[2][2] = {{nz00, nz01}, {nz10, nz11}};
#pragma unroll
        for (int nt = 0; nt < 2; nt++)
#pragma unroll
            for (int h = 0; h < 2; h++) {
                u64 logdx = mul2_(sub2_(mu2[nt][h], xt[nt][h]), sinv2[nt][h]);
                u64 diff  = sub2_(logdx, sc[nt][h]);
                err2[nt][h] = fma2_(diff, diff, err2[nt][h]);
                u64 x = fma2_(mu2[nt][h], dt2, xt[nt][h]);
                x = fma2_(sc[nt][h], hv2[nt][h], x);
                xt[nt][h] = fma2_(nz[nt][h], ssd2[nt][h], x);
            }
    }

    // ---- outputs (scatter from fragment layout) ----
    const float inv_n = 1.0f / (float)NSTEPS;
#pragma unroll
    for (int h = 0; h < 2; h++) {
        int bb = (h == 0) ? cA : cB;
        float* oS = out + ((size_t)bb * MAXLEN + l) * LATENT;
        float* oE = oS + (size_t)BATCH * MAXLEN * LATENT;
        float x0, x1, e0, e1;
        upk(xt[0][h], x0, x1);
        upk(err2[0][h], e0, e1);
        oS[gc]     = x0;
        oS[gc + 4] = x1;
        oE[gc]     = e0 * inv_n;
        oE[gc + 4] = e1 * inv_n;
        if (gc < 2) {
            upk(xt[1][h], x0, x1);
            upk(err2[1][h], e0, e1);
            oS[8 + gc] = x0;
            oE[8 + gc] = e0 * inv_n;
        }
    }
}

extern "C" void kernel_launch(void* const* d_in, const int* in_sizes, int n_in,
                              void* d_out, int out_size)
{
    const float* zm    = (const float*)d_in[0];  // [512,80,10]
    const float* zlv   = (const float*)d_in[1];  // [512,80,10]
    const float* W1    = (const float*)d_in[2];  // [11,64]
    const float* b1    = (const float*)d_in[3];  // [64]
    const float* W2    = (const float*)d_in[4];  // [64,10]
    const float* b2    = (const float*)d_in[5];  // [10]
    const float* noise = (const float*)d_in[6];  // [80,100,512,10]
    float* out = (float*)d_out;                  // [2,512,80,10]

    const int nblocks = BATCH * MAXLEN / 16;     // 2560 warps, 16 chains each
    vae_mma_kernel<<<nblocks, 32>>>(zm, zlv, W1, b1, W2, b2, noise, out);
}

// round 8
// speedup vs baseline: 1.5337x; 1.5337x over previous
#include <cuda_runtime.h>

#define LATENT  10
#define MAXLEN  80
#define BATCH   512
#define NSTEPS  100
#define HID     64
#define DTC     0.01f

typedef unsigned long long u64;
typedef unsigned int u32;

// ---------------- packed f32x2 helpers (sm_100+) ----------------
__device__ __forceinline__ u64 pk(float x, float y) {
    u64 r; asm("mov.b64 %0, {%1, %2};" : "=l"(r) : "f"(x), "f"(y)); return r;
}
__device__ __forceinline__ void upk(u64 a, float& x, float& y) {
    asm("mov.b64 {%0, %1}, %2;" : "=f"(x), "=f"(y) : "l"(a));
}
__device__ __forceinline__ u64 fma2_(u64 a, u64 b, u64 c) {
    u64 d; asm("fma.rn.f32x2 %0, %1, %2, %3;" : "=l"(d) : "l"(a), "l"(b), "l"(c)); return d;
}
__device__ __forceinline__ u64 mul2_(u64 a, u64 b) {
    u64 d; asm("mul.rn.f32x2 %0, %1, %2;" : "=l"(d) : "l"(a), "l"(b)); return d;
}
__device__ __forceinline__ u64 sub2_(u64 a, u64 b) {
    u64 d; asm("sub.rn.f32x2 %0, %1, %2;" : "=l"(d) : "l"(a), "l"(b)); return d;
}

// ---------------- tf32 helpers ----------------
__device__ __forceinline__ u32 cvt_tf32(float x) {
    u32 r; asm("cvt.rna.tf32.f32 %0, %1;" : "=r"(r) : "f"(x)); return r;
}
__device__ __forceinline__ void split_tf32(float x, u32& hi, u32& lo) {
    hi = cvt_tf32(x);
    lo = cvt_tf32(x - __uint_as_float(hi));
}

__device__ __forceinline__ void mma8(float* c, u32 a0, u32 a1, u32 a2, u32 a3,
                                     u32 b0, u32 b1) {
    asm("mma.sync.aligned.m16n8k8.row.col.f32.tf32.tf32.f32 "
        "{%0,%1,%2,%3}, {%4,%5,%6,%7}, {%8,%9}, {%0,%1,%2,%3};"
        : "+f"(c[0]), "+f"(c[1]), "+f"(c[2]), "+f"(c[3])
        : "r"(a0), "r"(a1), "r"(a2), "r"(a3), "r"(b0), "r"(b1));
}

// per-(chain, d) SDE constants
__device__ __forceinline__ void prep_cd(const float* __restrict__ zm,
                                        const float* __restrict__ zlv,
                                        int bb, int l, int d,
                                        float& mu, float& sinv, float& ssd) {
    const float* zmr = zm  + ((size_t)bb * MAXLEN + l) * LATENT;
    const float* zvr = zlv + ((size_t)bb * MAXLEN + l) * LATENT;
    float zmc = zmr[d];
    float zmp = (l > 0) ? zmr[d - LATENT] : 0.f;
    mu = zmc - zmp;
    float av = (l > 0) ? zvr[d - LATENT] : 0.f;
    float bv = zvr[d];
    float mx = fmaxf(av, bv);
    float sg = mx + log1pf(expf(-fabsf(av - bv)));   // logaddexp
    float sstd = expf(0.5f * sg);
    sinv = 1.f / sg;
    ssd  = sstd * 0.1f;                              // sigma_std * sqrt(dt)
}

// One warp = 16 chains (same l). MLP via m16n8k8 tf32 MMA.
// Weights are register B-fragments split hi+lo (exact fp32 weights across two
// MMAs); MLP *inputs* are single tf32 (rna) — only input truncation error.
// SDE state stays in MMA C-layout (latent dim permuted) so the score output
// fragment is directly the next step's A fragment.
__global__ void __launch_bounds__(32)
vae_mma2_kernel(const float* __restrict__ zm,
                const float* __restrict__ zlv,
                const float* __restrict__ W1,
                const float* __restrict__ b1,
                const float* __restrict__ W2,
                const float* __restrict__ b2,
                const float* __restrict__ noise,
                float* __restrict__ out)
{
    const int lane = threadIdx.x;
    const int r  = lane >> 2;
    const int gc = lane & 3;
    const int base = blockIdx.x * 16;
    const int l   = base >> 9;          // uniform per warp (16 | 512)
    const int bb0 = base & 511;
    const int cA  = bb0 + r;
    const int cB  = bb0 + r + 8;

    // hidden-unit permutation: B-col n (=r) -> j_local
    const int jl = (r & 1) ? (r >> 1) + 4 : (r >> 1);

    // ---- static weight fragments (hi+lo split => exact fp32 weights) ----
    u32 B1h0[8][2], B1l0[8][2];       // layer1 kt0 (features 0-7)
    u32 B1h1[8],    B1l1[8];          // layer1 kt1 reg0 (features 8-11); reg1 = 0
    u32 B2h[8][2][2], B2l[8][2][2];   // layer2 [jt][nt][reg]

#pragma unroll
    for (int jt = 0; jt < 8; jt++) {
        int j = 8 * jt + jl;
        split_tf32(W1[gc * HID + j],       B1h0[jt][0], B1l0[jt][0]);
        split_tf32(W1[(gc + 4) * HID + j], B1h0[jt][1], B1l0[jt][1]);
        float wt = (gc == 3) ? b1[j] : W1[(8 + gc) * HID + j];
        split_tf32(wt, B1h1[jt], B1l1[jt]);
#pragma unroll
        for (int nt = 0; nt < 2; nt++) {
            int d = (nt == 0) ? jl : ((jl < 2) ? 8 + jl : -1);
            float v0 = (d >= 0) ? W2[(8 * jt + gc) * LATENT + d]     : 0.f;
            float v1 = (d >= 0) ? W2[(8 * jt + gc + 4) * LATENT + d] : 0.f;
            split_tf32(v0, B2h[jt][nt][0], B2l[jt][nt][0]);
            split_tf32(v1, B2h[jt][nt][1], B2l[jt][nt][1]);
        }
    }

    // ---- SDE state in fragment layout ----
    u64 xt[2][2], mu2[2][2], sinv2[2][2], ssd2[2][2], err2[2][2];
#pragma unroll
    for (int h = 0; h < 2; h++) {
        int bb = (h == 0) ? cA : cB;
        float m0, s0, w0, m1, s1, w1;
        prep_cd(zm, zlv, bb, l, gc,     m0, s0, w0);
        prep_cd(zm, zlv, bb, l, gc + 4, m1, s1, w1);
        mu2[0][h]   = pk(m0, m1);
        sinv2[0][h] = pk(s0, s1);
        ssd2[0][h]  = pk(w0, w1);
        xt[0][h]    = mu2[0][h];
        err2[0][h]  = 0ULL;
        if (gc < 2) {
            prep_cd(zm, zlv, bb, l, 8 + gc, m0, s0, w0);
        } else { m0 = 0.f; s0 = 0.f; w0 = 0.f; }
        mu2[1][h]   = pk(m0, 0.f);
        sinv2[1][h] = pk(s0, 0.f);
        ssd2[1][h]  = pk(w0, 0.f);
        xt[1][h]    = mu2[1][h];
        err2[1][h]  = 0ULL;
    }
    const u64 dt2 = pk(DTC, DTC);
    const u64 h05 = pk(0.5f, 0.5f);

    // bias values in S C-layout
    const float bs0 = b2[gc];
    const float bs1 = b2[gc + 4];
    const float bs2 = (gc < 2) ? b2[8 + gc] : 0.f;

    const float* nzbase = noise + (size_t)l * NSTEPS * BATCH * LATENT;

#pragma unroll 1
    for (int s = 0; s < NSTEPS; s++) {
        // noise for this step (fragment layout, scalar gathers)
        const float* nA = nzbase + (size_t)s * BATCH * LATENT + cA * LATENT;
        const float* nB = nA + 8 * LATENT;
        u64 nz00 = pk(nA[gc], nA[gc + 4]);
        u64 nz01 = pk(nB[gc], nB[gc + 4]);
        u64 nz10 = (gc < 2) ? pk(nA[8 + gc], 0.f) : 0ULL;
        u64 nz11 = (gc < 2) ? pk(nB[8 + gc], 0.f) : 0ULL;

        const float tt = (float)(l + s) * DTC;

        // A1 kt0 = xt state, single tf32 (rna)
        float xA0, xA1, xB0, xB1;
        upk(xt[0][0], xA0, xA1);
        upk(xt[0][1], xB0, xB1);
        u32 a0h = cvt_tf32(xA0);
        u32 a1h = cvt_tf32(xB0);
        u32 a2h = cvt_tf32(xA1);
        u32 a3h = cvt_tf32(xB1);

        // A1 kt1: cols 8+gc = (xt8, xt9, t, 1); cols 12+gc = 0
        float xA8, xB8, dmy;
        upk(xt[1][0], xA8, dmy);
        upk(xt[1][1], xB8, dmy);
        float sA0 = __shfl_sync(0xffffffffu, xA8, lane & ~3);
        float sA1 = __shfl_sync(0xffffffffu, xA8, (lane & ~3) | 1);
        float sB0 = __shfl_sync(0xffffffffu, xB8, lane & ~3);
        float sB1 = __shfl_sync(0xffffffffu, xB8, (lane & ~3) | 1);
        float f0 = (gc == 0) ? sA0 : (gc == 1) ? sA1 : (gc == 2) ? tt : 1.0f;
        float f1 = (gc == 0) ? sB0 : (gc == 1) ? sB1 : (gc == 2) ? tt : 1.0f;
        u32 e0h = cvt_tf32(f0);
        u32 e1h = cvt_tf32(f1);

        // layer-2 accumulators (hi and lo weight streams kept separate for ILP)
        float Sa[2][4] = {{bs0, bs1, bs0, bs1}, {bs2, 0.f, bs2, 0.f}};
        float Sb[2][4] = {{0.f,0.f,0.f,0.f},{0.f,0.f,0.f,0.f}};

#pragma unroll
        for (int jt = 0; jt < 8; jt++) {
            float C[4] = {0.f, 0.f, 0.f, 0.f};
            mma8(C, a0h, a1h, a2h, a3h, B1h0[jt][0], B1h0[jt][1]);   // Ahi*W1hi kt0
            mma8(C, e0h, e1h, 0u,  0u,  B1h1[jt],    0u);            // Ehi*W1hi kt1
            mma8(C, a0h, a1h, a2h, a3h, B1l0[jt][0], B1l0[jt][1]);   // Ahi*W1lo kt0
            mma8(C, e0h, e1h, 0u,  0u,  B1l1[jt],    0u);            // Ehi*W1lo kt1

            float h0 = fmaxf(C[0], 0.f);
            float h1 = fmaxf(C[1], 0.f);
            float h2 = fmaxf(C[2], 0.f);
            float h3 = fmaxf(C[3], 0.f);

            // H C-fragment -> A2 fragment: (a0,a1,a2,a3) = (c0,c2,c1,c3)
            u32 H0h = cvt_tf32(h0);
            u32 H1h = cvt_tf32(h2);
            u32 H2h = cvt_tf32(h1);
            u32 H3h = cvt_tf32(h3);

#pragma unroll
            for (int nt = 0; nt < 2; nt++) {
                mma8(Sa[nt], H0h, H1h, H2h, H3h, B2h[jt][nt][0], B2h[jt][nt][1]);
                mma8(Sb[nt], H0h, H1h, H2h, H3h, B2l[jt][nt][0], B2l[jt][nt][1]);
            }
        }

        // combine hi+lo partial scores -> packed (d0,d1) pairs
        u64 sc[2][2];
#pragma unroll
        for (int nt = 0; nt < 2; nt++) {
            sc[nt][0] = pk(Sa[nt][0] + Sb[nt][0], Sa[nt][1] + Sb[nt][1]);
            sc[nt][1] = pk(Sa[nt][2] + Sb[nt][2], Sa[nt][3] + Sb[nt][3]);
        }

        // SDE update + score error (packed); hv = 0.5*ssd^2 computed on the fly
        u64 nz[2][2] = {{nz00, nz01}, {nz10, nz11}};
#pragma unroll
        for (int nt = 0; nt < 2; nt++)
#pragma unroll
            for (int h = 0; h < 2; h++) {
                u64 logdx = mul2_(sub2_(mu2[nt][h], xt[nt][h]), sinv2[nt][h]);
                u64 diff  = sub2_(logdx, sc[nt][h]);
                err2[nt][h] = fma2_(diff, diff, err2[nt][h]);
                u64 x  = fma2_(mu2[nt][h], dt2, xt[nt][h]);
                u64 t1 = mul2_(sc[nt][h], ssd2[nt][h]);
                u64 t2 = mul2_(t1, ssd2[nt][h]);
                x = fma2_(t2, h05, x);                       // + 0.5*var*score*dt
                xt[nt][h] = fma2_(nz[nt][h], ssd2[nt][h], x);
            }
    }

    // ---- outputs (scatter from fragment layout) ----
    const float inv_n = 1.0f / (float)NSTEPS;
#pragma unroll
    for (int h = 0; h < 2; h++) {
        int bb = (h == 0) ? cA : cB;
        float* oS = out + ((size_t)bb * MAXLEN + l) * LATENT;
        float* oE = oS + (size_t)BATCH * MAXLEN * LATENT;
        float x0, x1, e0, e1;
        upk(xt[0][h], x0, x1);
        upk(err2[0][h], e0, e1);
        oS[gc]     = x0;
        oS[gc + 4] = x1;
        oE[gc]     = e0 * inv_n;
        oE[gc + 4] = e1 * inv_n;
        if (gc < 2) {
            upk(xt[1][h], x0, x1);
            upk(err2[1][h], e0, e1);
            oS[8 + gc] = x0;
            oE[8 + gc] = e0 * inv_n;
        }
    }
}

extern "C" void kernel_launch(void* const* d_in, const int* in_sizes, int n_in,
                              void* d_out, int out_size)
{
    const float* zm    = (const float*)d_in[0];  // [512,80,10]
    const float* zlv   = (const float*)d_in[1];  // [512,80,10]
    const float* W1    = (const float*)d_in[2];  // [11,64]
    const float* b1    = (const float*)d_in[3];  // [64]
    const float* W2    = (const float*)d_in[4];  // [64,10]
    const float* b2    = (const float*)d_in[5];  // [10]
    const float* noise = (const float*)d_in[6];  // [80,100,512,10]
    float* out = (float*)d_out;                  // [2,512,80,10]

    const int nblocks = BATCH * MAXLEN / 16;     // 2560 warps, 16 chains each
    vae_mma2_kernel<<<nblocks, 32>>>(zm, zlv, W1, b1, W2, b2, noise, out);
}

// round 9
// speedup vs baseline: 1.8540x; 1.2088x over previous
#include <cuda_runtime.h>

#define LATENT  10
#define MAXLEN  80
#define BATCH   512
#define NSTEPS  100
#define HID     64
#define DTC     0.01f

typedef unsigned long long u64;
typedef unsigned int u32;

// ---------------- packed f32x2 helpers (sm_100+) ----------------
__device__ __forceinline__ u64 pk(float x, float y) {
    u64 r; asm("mov.b64 %0, {%1, %2};" : "=l"(r) : "f"(x), "f"(y)); return r;
}
__device__ __forceinline__ void upk(u64 a, float& x, float& y) {
    asm("mov.b64 {%0, %1}, %2;" : "=f"(x), "=f"(y) : "l"(a));
}
__device__ __forceinline__ u64 fma2_(u64 a, u64 b, u64 c) {
    u64 d; asm("fma.rn.f32x2 %0, %1, %2, %3;" : "=l"(d) : "l"(a), "l"(b), "l"(c)); return d;
}
__device__ __forceinline__ u64 mul2_(u64 a, u64 b) {
    u64 d; asm("mul.rn.f32x2 %0, %1, %2;" : "=l"(d) : "l"(a), "l"(b)); return d;
}
__device__ __forceinline__ u64 sub2_(u64 a, u64 b) {
    u64 d; asm("sub.rn.f32x2 %0, %1, %2;" : "=l"(d) : "l"(a), "l"(b)); return d;
}

// ---------------- tf32 helpers ----------------
__device__ __forceinline__ u32 cvt_tf32(float x) {
    u32 r; asm("cvt.rna.tf32.f32 %0, %1;" : "=r"(r) : "f"(x)); return r;
}

__device__ __forceinline__ void mma8(float* c, u32 a0, u32 a1, u32 a2, u32 a3,
                                     u32 b0, u32 b1) {
    asm("mma.sync.aligned.m16n8k8.row.col.f32.tf32.tf32.f32 "
        "{%0,%1,%2,%3}, {%4,%5,%6,%7}, {%8,%9}, {%0,%1,%2,%3};"
        : "+f"(c[0]), "+f"(c[1]), "+f"(c[2]), "+f"(c[3])
        : "r"(a0), "r"(a1), "r"(a2), "r"(a3), "r"(b0), "r"(b1));
}

// per-(chain, d) SDE constants
__device__ __forceinline__ void prep_cd(const float* __restrict__ zm,
                                        const float* __restrict__ zlv,
                                        int bb, int l, int d,
                                        float& mu, float& sinv, float& ssd) {
    const float* zmr = zm  + ((size_t)bb * MAXLEN + l) * LATENT;
    const float* zvr = zlv + ((size_t)bb * MAXLEN + l) * LATENT;
    float zmc = zmr[d];
    float zmp = (l > 0) ? zmr[d - LATENT] : 0.f;
    mu = zmc - zmp;
    float av = (l > 0) ? zvr[d - LATENT] : 0.f;
    float bv = zvr[d];
    float mx = fmaxf(av, bv);
    float sg = mx + log1pf(expf(-fabsf(av - bv)));   // logaddexp
    float sstd = expf(0.5f * sg);
    sinv = 1.f / sg;
    ssd  = sstd * 0.1f;                              // sigma_std * sqrt(dt)
}

// One warp = 16 chains (same l). MLP via m16n8k8 tf32 MMA, single-tf32
// weights in register B-fragments. SDE state lives in MMA C-layout (latent
// dim permuted) so the score output fragment IS the next step's A fragment.
// Layer-2 accumulation split into two chains (even/odd jt) for ILP.
__global__ void __launch_bounds__(32)
vae_mma3_kernel(const float* __restrict__ zm,
                const float* __restrict__ zlv,
                const float* __restrict__ W1,
                const float* __restrict__ b1,
                const float* __restrict__ W2,
                const float* __restrict__ b2,
                const float* __restrict__ noise,
                float* __restrict__ out)
{
    const int lane = threadIdx.x;
    const int r  = lane >> 2;
    const int gc = lane & 3;
    const int base = blockIdx.x * 16;
    const int l   = base >> 9;          // uniform per warp (16 | 512)
    const int bb0 = base & 511;
    const int cA  = bb0 + r;
    const int cB  = bb0 + r + 8;

    // hidden-unit permutation: B-col n (=r) -> j_local
    const int jl = (r & 1) ? (r >> 1) + 4 : (r >> 1);

    // ---- static weight fragments (single tf32) ----
    u32 B1h0[8][2];                   // layer1 kt0 (features 0-7)
    u32 B1h1[8];                      // layer1 kt1 reg0 (features 8-11); reg1 = 0
    u32 B2h[8][2][2];                 // layer2 [jt][nt][reg]

#pragma unroll
    for (int jt = 0; jt < 8; jt++) {
        int j = 8 * jt + jl;
        B1h0[jt][0] = cvt_tf32(W1[gc * HID + j]);
        B1h0[jt][1] = cvt_tf32(W1[(gc + 4) * HID + j]);
        float wt = (gc == 3) ? b1[j] : W1[(8 + gc) * HID + j];
        B1h1[jt] = cvt_tf32(wt);
#pragma unroll
        for (int nt = 0; nt < 2; nt++) {
            int d = (nt == 0) ? jl : ((jl < 2) ? 8 + jl : -1);
            float v0 = (d >= 0) ? W2[(8 * jt + gc) * LATENT + d]     : 0.f;
            float v1 = (d >= 0) ? W2[(8 * jt + gc + 4) * LATENT + d] : 0.f;
            B2h[jt][nt][0] = cvt_tf32(v0);
            B2h[jt][nt][1] = cvt_tf32(v1);
        }
    }

    // ---- SDE state in fragment layout ----
    u64 xt[2][2], mu2[2][2], sinv2[2][2], ssd2[2][2], err2[2][2];
#pragma unroll
    for (int h = 0; h < 2; h++) {
        int bb = (h == 0) ? cA : cB;
        float m0, s0, w0, m1, s1, w1;
        prep_cd(zm, zlv, bb, l, gc,     m0, s0, w0);
        prep_cd(zm, zlv, bb, l, gc + 4, m1, s1, w1);
        mu2[0][h]   = pk(m0, m1);
        sinv2[0][h] = pk(s0, s1);
        ssd2[0][h]  = pk(w0, w1);
        xt[0][h]    = mu2[0][h];
        err2[0][h]  = 0ULL;
        if (gc < 2) {
            prep_cd(zm, zlv, bb, l, 8 + gc, m0, s0, w0);
        } else { m0 = 0.f; s0 = 0.f; w0 = 0.f; }
        mu2[1][h]   = pk(m0, 0.f);
        sinv2[1][h] = pk(s0, 0.f);
        ssd2[1][h]  = pk(w0, 0.f);
        xt[1][h]    = mu2[1][h];
        err2[1][h]  = 0ULL;
    }
    const u64 dt2 = pk(DTC, DTC);
    const u64 h05 = pk(0.5f, 0.5f);

    // bias values in S C-layout
    const float bs0 = b2[gc];
    const float bs1 = b2[gc + 4];
    const float bs2 = (gc < 2) ? b2[8 + gc] : 0.f;

    const float* nzbase = noise + (size_t)l * NSTEPS * BATCH * LATENT;

#pragma unroll 1
    for (int s = 0; s < NSTEPS; s++) {
        // noise for this step (fragment layout, scalar gathers)
        const float* nA = nzbase + (size_t)s * BATCH * LATENT + cA * LATENT;
        const float* nB = nA + 8 * LATENT;
        u64 nz00 = pk(nA[gc], nA[gc + 4]);
        u64 nz01 = pk(nB[gc], nB[gc + 4]);
        u64 nz10 = (gc < 2) ? pk(nA[8 + gc], 0.f) : 0ULL;
        u64 nz11 = (gc < 2) ? pk(nB[8 + gc], 0.f) : 0ULL;

        const float tt = (float)(l + s) * DTC;

        // A1 kt0 = xt state, single tf32 (rna)
        float xA0, xA1, xB0, xB1;
        upk(xt[0][0], xA0, xA1);
        upk(xt[0][1], xB0, xB1);
        u32 a0h = cvt_tf32(xA0);
        u32 a1h = cvt_tf32(xB0);
        u32 a2h = cvt_tf32(xA1);
        u32 a3h = cvt_tf32(xB1);

        // A1 kt1: cols 8+gc = (xt8, xt9, t, 1); cols 12+gc = 0
        float xA8, xB8, dmy;
        upk(xt[1][0], xA8, dmy);
        upk(xt[1][1], xB8, dmy);
        float sA0 = __shfl_sync(0xffffffffu, xA8, lane & ~3);
        float sA1 = __shfl_sync(0xffffffffu, xA8, (lane & ~3) | 1);
        float sB0 = __shfl_sync(0xffffffffu, xB8, lane & ~3);
        float sB1 = __shfl_sync(0xffffffffu, xB8, (lane & ~3) | 1);
        float f0 = (gc == 0) ? sA0 : (gc == 1) ? sA1 : (gc == 2) ? tt : 1.0f;
        float f1 = (gc == 0) ? sB0 : (gc == 1) ? sB1 : (gc == 2) ? tt : 1.0f;
        u32 e0h = cvt_tf32(f0);
        u32 e1h = cvt_tf32(f1);

        // layer-2: two independent accumulator chains (even jt -> Sa, odd -> Sb)
        float Sa[2][4] = {{bs0, bs1, bs0, bs1}, {bs2, 0.f, bs2, 0.f}};
        float Sb[2][4] = {{0.f,0.f,0.f,0.f},{0.f,0.f,0.f,0.f}};

#pragma unroll
        for (int jt = 0; jt < 8; jt++) {
            float C[4] = {0.f, 0.f, 0.f, 0.f};
            mma8(C, a0h, a1h, a2h, a3h, B1h0[jt][0], B1h0[jt][1]);   // A*W1 kt0
            mma8(C, e0h, e1h, 0u,  0u,  B1h1[jt],    0u);            // E*W1 kt1

            float h0 = fmaxf(C[0], 0.f);
            float h1 = fmaxf(C[1], 0.f);
            float h2 = fmaxf(C[2], 0.f);
            float h3 = fmaxf(C[3], 0.f);

            // H C-fragment -> A2 fragment: (a0,a1,a2,a3) = (c0,c2,c1,c3)
            u32 H0h = cvt_tf32(h0);
            u32 H1h = cvt_tf32(h2);
            u32 H2h = cvt_tf32(h1);
            u32 H3h = cvt_tf32(h3);

            float* S0 = (jt & 1) ? Sb[0] : Sa[0];
            float* S1 = (jt & 1) ? Sb[1] : Sa[1];
            mma8(S0, H0h, H1h, H2h, H3h, B2h[jt][0][0], B2h[jt][0][1]);
            mma8(S1, H0h, H1h, H2h, H3h, B2h[jt][1][0], B2h[jt][1][1]);
        }

        // combine both chains -> packed (d0,d1) pairs
        u64 sc[2][2];
#pragma unroll
        for (int nt = 0; nt < 2; nt++) {
            sc[nt][0] = pk(Sa[nt][0] + Sb[nt][0], Sa[nt][1] + Sb[nt][1]);
            sc[nt][1] = pk(Sa[nt][2] + Sb[nt][2], Sa[nt][3] + Sb[nt][3]);
        }

        // SDE update + score error (packed); hv = 0.5*ssd^2 computed on the fly
        u64 nz[2][2] = {{nz00, nz01}, {nz10, nz11}};
#pragma unroll
        for (int nt = 0; nt < 2; nt++)
#pragma unroll
            for (int h = 0; h < 2; h++) {
                u64 logdx = mul2_(sub2_(mu2[nt][h], xt[nt][h]), sinv2[nt][h]);
                u64 diff  = sub2_(logdx, sc[nt][h]);
                err2[nt][h] = fma2_(diff, diff, err2[nt][h]);
                u64 x  = fma2_(mu2[nt][h], dt2, xt[nt][h]);
                u64 t1 = mul2_(sc[nt][h], ssd2[nt][h]);
                u64 t2 = mul2_(t1, ssd2[nt][h]);
                x = fma2_(t2, h05, x);                       // + 0.5*var*score*dt
                xt[nt][h] = fma2_(nz[nt][h], ssd2[nt][h], x);
            }
    }

    // ---- outputs (scatter from fragment layout) ----
    const float inv_n = 1.0f / (float)NSTEPS;
#pragma unroll
    for (int h = 0; h < 2; h++) {
        int bb = (h == 0) ? cA : cB;
        float* oS = out + ((size_t)bb * MAXLEN + l) * LATENT;
        float* oE = oS + (size_t)BATCH * MAXLEN * LATENT;
        float x0, x1, e0, e1;
        upk(xt[0][h], x0, x1);
        upk(err2[0][h], e0, e1);
        oS[gc]     = x0;
        oS[gc + 4] = x1;
        oE[gc]     = e0 * inv_n;
        oE[gc + 4] = e1 * inv_n;
        if (gc < 2) {
            upk(xt[1][h], x0, x1);
            upk(err2[1][h], e0, e1);
            oS[8 + gc] = x0;
            oE[8 + gc] = e0 * inv_n;
        }
    }
}

extern "C" void kernel_launch(void* const* d_in, const int* in_sizes, int n_in,
                              void* d_out, int out_size)
{
    const float* zm    = (const float*)d_in[0];  // [512,80,10]
    const float* zlv   = (const float*)d_in[1];  // [512,80,10]
    const float* W1    = (const float*)d_in[2];  // [11,64]
    const float* b1    = (const float*)d_in[3];  // [64]
    const float* W2    = (const float*)d_in[4];  // [64,10]
    const float* b2    = (const float*)d_in[5];  // [10]
    const float* noise = (const float*)d_in[6];  // [80,100,512,10]
    float* out = (float*)d_out;                  // [2,512,80,10]

    const int nblocks = BATCH * MAXLEN / 16;     // 2560 warps, 16 chains each
    vae_mma3_kernel<<<nblocks, 32>>>(zm, zlv, W1, b1, W2, b2, noise, out);
}